// round 4
// baseline (speedup 1.0000x reference)
#include <cuda_runtime.h>
#include <cuda_bf16.h>

// AttentionPooling: B=64, S=4096, D=256, fp32.
//   LN(x) over D -> Dense(1) score -> softmax over S -> out[b,d] = sum_s x_s * w_s
// One pass over x. Per-warp 3-deep cp.async smem pipeline keeps ~12KB/warp of
// loads in flight (vs 1KB with register double-buffering), online softmax with
// 4-row batching, split-chunk partials combined by the last-arriving block.

#define BDIM   64
#define SDIM   4096
#define DDIM   256
#define CHUNKS 32
#define RPC    (SDIM / CHUNKS)   /* 128 rows per block */
#define WARPS  8
#define NTHR   (WARPS * 32)
#define RPW    (RPC / WARPS)     /* 16 rows per warp */
#define RB     4                 /* rows per stage */
#define NIT    (RPW / RB)        /* 4 stages of work per warp */
#define DEPTH  3                 /* pipeline depth (smem ring) */
#define LN_EPS 1e-3f

#define STAGE_FLOATS (RB * DDIM)            /* 1024 floats = 4KB */
#define WARP_FLOATS  (DEPTH * STAGE_FLOATS) /* 12KB per warp */
#define DSMEM_BYTES  (WARPS * WARP_FLOATS * 4)  /* 96KB per CTA */

// Split-softmax partial scratch + completion counters (static device globals).
__device__ float g_pacc[BDIM * CHUNKS * DDIM];   // 2 MB
__device__ float g_pm[BDIM * CHUNKS];
__device__ float g_pl[BDIM * CHUNKS];
__device__ int   g_cnt[BDIM];                    // zero-init; self-resetting

__device__ __forceinline__ float warp_sum(float v) {
    #pragma unroll
    for (int o = 16; o > 0; o >>= 1) v += __shfl_xor_sync(0xffffffffu, v, o);
    return v;
}

__device__ __forceinline__ unsigned smem_u32(const void* p) {
    return (unsigned)__cvta_generic_to_shared(p);
}

__device__ __forceinline__ void cp16(unsigned smem_dst, const void* gsrc) {
    asm volatile("cp.async.cg.shared.global [%0], [%1], 16;\n"
                 :: "r"(smem_dst), "l"(gsrc) : "memory");
}
__device__ __forceinline__ void cp_commit() {
    asm volatile("cp.async.commit_group;\n" ::: "memory");
}
template <int N>
__device__ __forceinline__ void cp_wait() {
    asm volatile("cp.async.wait_group %0;\n" :: "n"(N) : "memory");
}

__global__ __launch_bounds__(NTHR, 2)
void ap_fused(const float* __restrict__ x, const float* __restrict__ mask,
              const float* __restrict__ gamma, const float* __restrict__ beta,
              const float* __restrict__ w, const float* __restrict__ bias,
              float* __restrict__ out)
{
    extern __shared__ float dynsm[];   // [WARPS][DEPTH][RB][DDIM]

    const int b     = blockIdx.y;
    const int chunk = blockIdx.x;
    const int wid   = threadIdx.x >> 5;
    const int lid   = threadIdx.x & 31;

    float* warp_buf = dynsm + wid * WARP_FLOATS;

    // Per-lane parameter slices: d = lid*4..lid*4+3 and 128+lid*4..
    const float4 gm0 = __ldg(((const float4*)gamma) + lid);
    const float4 gm1 = __ldg(((const float4*)gamma) + 32 + lid);
    const float4 ww0 = __ldg(((const float4*)w) + lid);
    const float4 ww1 = __ldg(((const float4*)w) + 32 + lid);
    const float4 bt0 = __ldg(((const float4*)beta) + lid);
    const float4 bt1 = __ldg(((const float4*)beta) + 32 + lid);

    const float gw0[4] = {gm0.x*ww0.x, gm0.y*ww0.y, gm0.z*ww0.z, gm0.w*ww0.w};
    const float gw1[4] = {gm1.x*ww1.x, gm1.y*ww1.y, gm1.z*ww1.z, gm1.w*ww1.w};

    float sgw = gw0[0]+gw0[1]+gw0[2]+gw0[3] + gw1[0]+gw1[1]+gw1[2]+gw1[3];
    float bw  = bt0.x*ww0.x + bt0.y*ww0.y + bt0.z*ww0.z + bt0.w*ww0.w
              + bt1.x*ww1.x + bt1.y*ww1.y + bt1.z*ww1.z + bt1.w*ww1.w;
    sgw = warp_sum(sgw);
    bw  = warp_sum(bw);
    const float score_c = bw + __ldg(bias);

    const float* xb = x + (size_t)b * SDIM * DDIM;
    const float* mb = mask + (size_t)b * SDIM;

    const int row_base = chunk * RPC + wid * RPW;

    // Issue one stage: lane copies the exact 2x16B slices of each row that it
    // will later read (bytes [lid*16,+16) and [512+lid*16,+16)).
    auto issue_stage = [&](int st) {
        float* sb = warp_buf + (st % DEPTH) * STAGE_FLOATS;
        const int s0 = row_base + st * RB;
        #pragma unroll
        for (int k = 0; k < RB; k++) {
            const float* grow = xb + (size_t)(s0 + k) * DDIM;
            float* srow = sb + k * DDIM;
            cp16(smem_u32(srow + lid * 4),       grow + lid * 4);
            cp16(smem_u32(srow + 128 + lid * 4), grow + 128 + lid * 4);
        }
        cp_commit();
    };

    // Prologue: fill the ring.
    issue_stage(0);
    issue_stage(1);
    issue_stage(2);

    // Online softmax state (per warp; acc distributed across lanes)
    float m = -3.0e38f, l = 0.0f;
    float acc0[4] = {0.f, 0.f, 0.f, 0.f};
    float acc1[4] = {0.f, 0.f, 0.f, 0.f};

    #pragma unroll
    for (int it = 0; it < NIT; it++) {
        // Wait until stage `it` has landed. Pending groups after stage `it`
        // is min(DEPTH-1, NIT-1-it) -> compile-time constant per iteration.
        constexpr int waits[4] = {DEPTH - 1, DEPTH - 1, 1, 0};
        if      (waits[it] == 2) cp_wait<2>();
        else if (waits[it] == 1) cp_wait<1>();
        else                     cp_wait<0>();

        const float* sb = warp_buf + (it % DEPTH) * STAGE_FLOATS;
        const int s0 = row_base + it * RB;

        // Read this stage's rows (each lane reads only bytes it copied).
        float4 xv0[RB], xv1[RB];
        #pragma unroll
        for (int k = 0; k < RB; k++) {
            xv0[k] = *(const float4*)(sb + k * DDIM + lid * 4);
            xv1[k] = *(const float4*)(sb + k * DDIM + 128 + lid * 4);
        }

        // Refill the ring immediately.
        if (it + DEPTH < NIT) issue_stage(it + DEPTH);

        // Per-row partials: sum(x), sum(x^2), dot(x, gamma*w)
        float p1[RB], p2[RB], pd[RB];
        #pragma unroll
        for (int k = 0; k < RB; k++) {
            const float4 a = xv0[k], c = xv1[k];
            p1[k] = a.x + a.y + a.z + a.w + c.x + c.y + c.z + c.w;
            p2[k] = a.x*a.x + a.y*a.y + a.z*a.z + a.w*a.w
                  + c.x*c.x + c.y*c.y + c.z*c.z + c.w*c.w;
            pd[k] = a.x*gw0[0] + a.y*gw0[1] + a.z*gw0[2] + a.w*gw0[3]
                  + c.x*gw1[0] + c.y*gw1[1] + c.z*gw1[2] + c.w*gw1[3];
        }
        // 12 concurrent butterfly chains
        #pragma unroll
        for (int o = 16; o > 0; o >>= 1) {
            #pragma unroll
            for (int k = 0; k < RB; k++) {
                p1[k] += __shfl_xor_sync(0xffffffffu, p1[k], o);
                p2[k] += __shfl_xor_sync(0xffffffffu, p2[k], o);
                pd[k] += __shfl_xor_sync(0xffffffffu, pd[k], o);
            }
        }

        const float4 mv = __ldg((const float4*)(mb + s0));
        const float mk[RB] = {mv.x, mv.y, mv.z, mv.w};

        float sc[RB];
        #pragma unroll
        for (int k = 0; k < RB; k++) {
            const float mu   = p1[k] * (1.0f / DDIM);
            const float var  = p2[k] * (1.0f / DDIM) - mu * mu;
            const float rstd = rsqrtf(var + LN_EPS);
            sc[k] = rstd * (pd[k] - mu * sgw) + score_c
                  + (1.0f - mk[k]) * (-1.0e9f);
        }

        // One rescale per 4 rows
        float mnew = m;
        #pragma unroll
        for (int k = 0; k < RB; k++) mnew = fmaxf(mnew, sc[k]);
        const float cs = __expf(m - mnew);
        float p[RB];
        float psum = 0.0f;
        #pragma unroll
        for (int k = 0; k < RB; k++) { p[k] = __expf(sc[k] - mnew); psum += p[k]; }
        l = l * cs + psum;
        m = mnew;

        #pragma unroll
        for (int j = 0; j < 4; j++) {
            float a0 = acc0[j] * cs;
            float a1 = acc1[j] * cs;
            a0 = fmaf(p[0], ((const float*)&xv0[0])[j], a0);
            a0 = fmaf(p[1], ((const float*)&xv0[1])[j], a0);
            a0 = fmaf(p[2], ((const float*)&xv0[2])[j], a0);
            a0 = fmaf(p[3], ((const float*)&xv0[3])[j], a0);
            a1 = fmaf(p[0], ((const float*)&xv1[0])[j], a1);
            a1 = fmaf(p[1], ((const float*)&xv1[1])[j], a1);
            a1 = fmaf(p[2], ((const float*)&xv1[2])[j], a1);
            a1 = fmaf(p[3], ((const float*)&xv1[3])[j], a1);
            acc0[j] = a0;
            acc1[j] = a1;
        }
    }

    // Combine the 8 warps of this block. The reduction buffer aliases the
    // cp.async ring (all stage data fully consumed; sync first).
    __syncthreads();
    float* sm_acc = dynsm;                 // [WARPS][DDIM] = 8KB, aliases ring
    __shared__ float sm_m[WARPS];
    __shared__ float sm_l[WARPS];

    #pragma unroll
    for (int j = 0; j < 4; j++) sm_acc[wid * DDIM + lid * 4 + j]       = acc0[j];
    #pragma unroll
    for (int j = 0; j < 4; j++) sm_acc[wid * DDIM + 128 + lid * 4 + j] = acc1[j];
    if (lid == 0) { sm_m[wid] = m; sm_l[wid] = l; }
    __syncthreads();

    const int d = threadIdx.x;               // 0..255
    float M = -3.0e38f;
    #pragma unroll
    for (int ww = 0; ww < WARPS; ww++) M = fmaxf(M, sm_m[ww]);
    float L = 0.0f, A = 0.0f;
    #pragma unroll
    for (int ww = 0; ww < WARPS; ww++) {
        const float e = __expf(sm_m[ww] - M);
        L += e * sm_l[ww];
        A += e * sm_acc[ww * DDIM + d];
    }
    const int pidx = b * CHUNKS + chunk;
    g_pacc[(size_t)pidx * DDIM + d] = A;
    if (threadIdx.x == 0) { g_pm[pidx] = M; g_pl[pidx] = L; }

    // --- Split-K style combine: last block for this batch does the reduction ---
    __threadfence();
    __shared__ int s_is_last;
    __syncthreads();
    if (threadIdx.x == 0) {
        const int old = atomicAdd(&g_cnt[b], 1);
        s_is_last = (old == CHUNKS - 1);
    }
    __syncthreads();

    if (s_is_last) {
        __threadfence();  // acquire: see all other blocks' partials
        float Mg = -3.0e38f;
        #pragma unroll
        for (int i = 0; i < CHUNKS; i++) Mg = fmaxf(Mg, g_pm[b * CHUNKS + i]);
        float Lg = 0.0f, Ag = 0.0f;
        #pragma unroll
        for (int i = 0; i < CHUNKS; i++) {
            const float e = __expf(g_pm[b * CHUNKS + i] - Mg);
            Lg += e * g_pl[b * CHUNKS + i];
            Ag += e * g_pacc[((size_t)(b * CHUNKS + i)) * DDIM + d];
        }
        out[b * DDIM + d] = Ag / Lg;
        __syncthreads();
        if (threadIdx.x == 0) g_cnt[b] = 0;   // reset for next graph replay
    }
}

extern "C" void kernel_launch(void* const* d_in, const int* in_sizes, int n_in,
                              void* d_out, int out_size)
{
    const float* x     = (const float*)d_in[0];
    const float* mask  = (const float*)d_in[1];
    const float* gamma = (const float*)d_in[2];
    const float* beta  = (const float*)d_in[3];
    const float* w     = (const float*)d_in[4];
    const float* bias  = (const float*)d_in[5];
    float* out = (float*)d_out;

    cudaFuncSetAttribute(ap_fused, cudaFuncAttributeMaxDynamicSharedMemorySize,
                         DSMEM_BYTES);

    dim3 grid(CHUNKS, BDIM);
    ap_fused<<<grid, NTHR, DSMEM_BYTES>>>(x, mask, gamma, beta, w, bias, out);
}